// round 4
// baseline (speedup 1.0000x reference)
#include <cuda_runtime.h>

// LIF scan: T=16, N = 4,194,304 sites. HBM-bound streaming (256 MiB in, 256 MiB out).
// R1 (plain loop,  occ 85%): DRAM 79.7%, ncu 76.7us
// R2 (TBATCH=8,    occ 64%): DRAM 80.3%, ncu 76.0us
// R3 (TBATCH=16,   occ 31%): DRAM 79.5%, ncu 76.7us
//   -> per-thread MLP/burst shape is irrelevant; ~6.3 TB/s is the mixed R/W ceiling.
// R4: kill the last structural loss — wave quantization. grid=4096 @ ~1184
// concurrent = 3.46 waves (partial last wave ~ 2-4% loss). New launch:
// grid = 1024 CTAs x 256 thr, __launch_bounds__(256,8) forces <=32 regs ->
// 8 CTAs/SM -> ALL CTAs resident in ONE wave. Grid-stride loop: every thread
// does exactly 4 float4 lanes. Perfect balance, no tail.

#ifndef LIF_T
#define LIF_T 16
#endif

__global__ void __launch_bounds__(256, 8) lif_kernel(
    const float4* __restrict__ in,   // [T, N/4] float4
    float4* __restrict__ out,        // [T, N/4] float4
    int n4)                          // N/4 = 1,048,576
{
    const int stride = gridDim.x * blockDim.x;    // 262,144
    const float decay = 0.5f;
    const float thr   = 1.0f;

    for (int i = blockIdx.x * blockDim.x + threadIdx.x; i < n4; i += stride) {
        const float4* __restrict__ ip = in + i;
        float4* __restrict__ op = out + i;

        float vx = 0.0f, vy = 0.0f, vz = 0.0f, vw = 0.0f;

        #pragma unroll
        for (int t = 0; t < LIF_T; ++t) {
            const float4 x = __ldcs(ip + (size_t)t * n4);

            vx = fmaf(vx, decay, x.x);
            vy = fmaf(vy, decay, x.y);
            vz = fmaf(vz, decay, x.z);
            vw = fmaf(vw, decay, x.w);

            const float sx = (vx >= thr) ? 1.0f : 0.0f;
            const float sy = (vy >= thr) ? 1.0f : 0.0f;
            const float sz = (vz >= thr) ? 1.0f : 0.0f;
            const float sw = (vw >= thr) ? 1.0f : 0.0f;

            vx -= sx * thr;
            vy -= sy * thr;
            vz -= sz * thr;
            vw -= sw * thr;

            float4 s;
            s.x = sx; s.y = sy; s.z = sz; s.w = sw;
            __stcs(op + (size_t)t * n4, s);
        }
    }
}

extern "C" void kernel_launch(void* const* d_in, const int* in_sizes, int n_in,
                              void* d_out, int out_size)
{
    const float* in = (const float*)d_in[0];
    float* out = (float*)d_out;

    const int total = in_sizes[0];            // T * N = 67,108,864
    const int n = total / LIF_T;              // N = 4,194,304 (sites)
    const int n4 = n / 4;                     // 1,048,576 float4 lanes

    const int block = 256;
    const int grid = 1024;                    // single wave @ 8 CTAs/SM, 4 lanes/thread

    lif_kernel<<<grid, block>>>((const float4*)in, (float4*)out, n4);
}

// round 5
// speedup vs baseline: 1.0450x; 1.0450x over previous
#include <cuda_runtime.h>

// LIF scan: T=16, N = 4,194,304 sites. HBM-bound streaming (256 MiB in, 256 MiB out).
// History (ncu dur / DRAM%):
//  R1 plain,  b256 g4096, occ85: 76.7us / 79.7%
//  R2 TB=8,   b256 g4096, occ64: 76.0us / 80.3%   <- best bench 82.4us
//  R3 TB=16,  b256 g4096, occ31: 76.7us / 79.5%
//  R4 stride, b256 g1024, occ80: 79.6us / 77.2%   <- grid-stride regressed
// MLP / turnaround / waves all non-binding. R5 tests the last axis:
// DRAM row-buffer locality. block=1024 -> each CTA covers 16KiB contiguous
// per plane (4x R2), TBATCH=8 phase-batched loads give long same-row bursts
// per plane-stream. One exact float4 lane per thread (grid*block == n4).

#ifndef LIF_T
#define LIF_T 16
#endif
#define TBATCH 8

__global__ void __launch_bounds__(1024, 1) lif_kernel(
    const float4* __restrict__ in,   // [T, N/4] float4
    float4* __restrict__ out,        // [T, N/4] float4
    int n4)                          // N/4 = 1,048,576
{
    const int i = blockIdx.x * blockDim.x + threadIdx.x;
    if (i >= n4) return;

    const float decay = 0.5f;
    const float thr   = 1.0f;

    float vx = 0.0f, vy = 0.0f, vz = 0.0f, vw = 0.0f;

    const float4* __restrict__ ip = in + i;
    float4* __restrict__ op = out + i;

    #pragma unroll
    for (int tb = 0; tb < LIF_T; tb += TBATCH) {
        // Phase 1: batched loads — 8 independent LDG.128, each plane-stream
        // gets a 16KiB-contiguous CTA footprint (long row-buffer runs).
        float4 x[TBATCH];
        #pragma unroll
        for (int j = 0; j < TBATCH; ++j) {
            x[j] = __ldcs(ip + (size_t)(tb + j) * n4);
        }

        // Phase 2: serial LIF chain in registers
        #pragma unroll
        for (int j = 0; j < TBATCH; ++j) {
            vx = fmaf(vx, decay, x[j].x);
            vy = fmaf(vy, decay, x[j].y);
            vz = fmaf(vz, decay, x[j].z);
            vw = fmaf(vw, decay, x[j].w);

            const float sx = (vx >= thr) ? 1.0f : 0.0f;
            const float sy = (vy >= thr) ? 1.0f : 0.0f;
            const float sz = (vz >= thr) ? 1.0f : 0.0f;
            const float sw = (vw >= thr) ? 1.0f : 0.0f;

            vx -= sx * thr;
            vy -= sy * thr;
            vz -= sz * thr;
            vw -= sw * thr;

            x[j].x = sx; x[j].y = sy; x[j].z = sz; x[j].w = sw;
        }

        // Phase 3: batched stores — 8 back-to-back STG.128
        #pragma unroll
        for (int j = 0; j < TBATCH; ++j) {
            __stcs(op + (size_t)(tb + j) * n4, x[j]);
        }
    }
}

extern "C" void kernel_launch(void* const* d_in, const int* in_sizes, int n_in,
                              void* d_out, int out_size)
{
    const float* in = (const float*)d_in[0];
    float* out = (float*)d_out;

    const int total = in_sizes[0];            // T * N = 67,108,864
    const int n = total / LIF_T;              // N = 4,194,304 (sites)
    const int n4 = n / 4;                     // 1,048,576 float4 lanes

    const int block = 1024;
    const int grid = n4 / block;              // 1024 — exactly one lane per thread

    lif_kernel<<<grid, block>>>((const float4*)in, (float4*)out, n4);
}